// round 1
// baseline (speedup 1.0000x reference)
#include <cuda_runtime.h>

// h: [N_ROWS, DIM] fp32; S: [DIM, DIM] fp32 diagonal ±1.
// out = h @ S.T = h * diag(S) broadcast over rows — pure streaming op.

#define MAX_DIM 8192
__device__ float g_signs[MAX_DIM];

__global__ void extract_diag_kernel(const float* __restrict__ S, int dim) {
    int i = blockIdx.x * blockDim.x + threadIdx.x;
    if (i < dim) {
        g_signs[i] = S[(long long)i * dim + i];
    }
}

__global__ void parity_scale_kernel(const float4* __restrict__ h,
                                    float4* __restrict__ out,
                                    long long n_vec4, int dim4) {
    long long idx = (long long)blockIdx.x * blockDim.x + threadIdx.x;
    long long stride = (long long)gridDim.x * blockDim.x;
    const float4* signs4 = reinterpret_cast<const float4*>(g_signs);
    for (; idx < n_vec4; idx += stride) {
        int col4 = (int)(idx % dim4);
        float4 v = h[idx];
        float4 s = signs4[col4];
        v.x *= s.x;
        v.y *= s.y;
        v.z *= s.z;
        v.w *= s.w;
        out[idx] = v;
    }
}

extern "C" void kernel_launch(void* const* d_in, const int* in_sizes, int n_in,
                              void* d_out, int out_size) {
    const float* h = (const float*)d_in[0];
    const float* S = (const float*)d_in[1];
    float* out = (float*)d_out;

    // in_sizes[1] = DIM*DIM
    int dim = 1;
    {
        long long s = in_sizes[1];
        // integer sqrt
        long long lo = 1, hi = 65536;
        while (lo < hi) {
            long long mid = (lo + hi + 1) / 2;
            if (mid * mid <= s) lo = mid; else hi = mid - 1;
        }
        dim = (int)lo;
    }

    long long total = in_sizes[0];        // N_ROWS * DIM
    long long n_vec4 = total / 4;
    int dim4 = dim / 4;

    extract_diag_kernel<<<(dim + 255) / 256, 256>>>(S, dim);

    int threads = 256;
    long long want_blocks = (n_vec4 + threads - 1) / threads;
    int blocks = (int)(want_blocks > 147456 ? 147456 : want_blocks);
    parity_scale_kernel<<<blocks, threads>>>(
        (const float4*)h, (float4*)out, n_vec4, dim4);
}

// round 2
// speedup vs baseline: 1.0780x; 1.0780x over previous
#include <cuda_runtime.h>

// h: [N_ROWS, DIM] fp32; S: [DIM, DIM] fp32 diagonal ±1.
// out = h @ S.T = h * diag(S) broadcast over rows — pure streaming op.
//
// Key trick: grid-stride is forced to be a multiple of dim4 (DIM/4 in float4
// units), so each thread's column-within-row is LOOP-INVARIANT. Signs are
// loaded once per thread directly from S's diagonal (L2-broadcast), and the
// mainloop is pure LDG.128 / FMUL / STG.128 with one 64-bit add.

__global__ void parity_scale_kernel(const float4* __restrict__ h,
                                    const float* __restrict__ S,
                                    float4* __restrict__ out,
                                    long long n_vec4, int dim4, int dim) {
    long long idx0 = (long long)blockIdx.x * blockDim.x + threadIdx.x;
    long long stride = (long long)gridDim.x * blockDim.x;  // multiple of dim4

    // Column (in float4 units) is invariant because stride % dim4 == 0.
    int col4 = (int)(idx0 % (long long)dim4);
    int c = col4 * 4;

    // Load the 4 diagonal entries for this thread's columns (L2-hot broadcast).
    float4 s;
    s.x = S[(long long)(c + 0) * dim + (c + 0)];
    s.y = S[(long long)(c + 1) * dim + (c + 1)];
    s.z = S[(long long)(c + 2) * dim + (c + 2)];
    s.w = S[(long long)(c + 3) * dim + (c + 3)];

    long long idx = idx0;
    #pragma unroll 4
    for (; idx < n_vec4; idx += stride) {
        float4 v = h[idx];
        v.x *= s.x;
        v.y *= s.y;
        v.z *= s.z;
        v.w *= s.w;
        out[idx] = v;
    }
}

static long long gcd_ll(long long a, long long b) {
    while (b) { long long t = a % b; a = b; b = t; }
    return a;
}

extern "C" void kernel_launch(void* const* d_in, const int* in_sizes, int n_in,
                              void* d_out, int out_size) {
    const float* h = (const float*)d_in[0];
    const float* S = (const float*)d_in[1];
    float* out = (float*)d_out;

    // in_sizes[1] = DIM*DIM -> integer sqrt
    int dim = 1;
    {
        long long s = in_sizes[1];
        long long lo = 1, hi = 65536;
        while (lo < hi) {
            long long mid = (lo + hi + 1) / 2;
            if (mid * mid <= s) lo = mid; else hi = mid - 1;
        }
        dim = (int)lo;
    }

    long long total = in_sizes[0];        // N_ROWS * DIM
    long long n_vec4 = total / 4;
    int dim4 = dim / 4;

    const int threads = 256;
    // blocks must satisfy (blocks*threads) % dim4 == 0 so col4 is loop-invariant.
    long long m = (long long)dim4 / gcd_ll(threads, dim4);  // block-count granularity

    // Target ~32 blocks per SM (148 SMs) for good occupancy + per-thread reuse.
    long long want = 148LL * 32;
    long long blocks = ((want + m - 1) / m) * m;
    // Don't exceed what's needed to cover the data once.
    long long cover = (n_vec4 + threads - 1) / threads;
    long long cover_r = ((cover + m - 1) / m) * m;
    if (blocks > cover_r) blocks = cover_r;
    if (blocks < m) blocks = m;

    parity_scale_kernel<<<(int)blocks, threads>>>(
        (const float4*)h, S, (float4*)out, n_vec4, dim4, dim);
}

// round 3
// speedup vs baseline: 1.1257x; 1.0442x over previous
#include <cuda_runtime.h>

// h: [N_ROWS, DIM] fp32; S: [DIM, DIM] fp32 diagonal ±1.
// out = h @ S.T = h * diag(S) broadcast over rows — pure streaming op.

// ---------------- Specialized kernel: exact shape, 8 iters, MLP=8 ----------
// Requires: n_vec4 == ITERS * TOTAL_THREADS, TOTAL_THREADS % dim4 == 0.
template <int ITERS>
__global__ __launch_bounds__(256)
void parity_scale_exact(const float4* __restrict__ h,
                        const float* __restrict__ S,
                        float4* __restrict__ out,
                        int dim4, int dim) {
    const long long stride = (long long)gridDim.x * blockDim.x;
    const long long idx0 = (long long)blockIdx.x * blockDim.x + threadIdx.x;

    // Column invariant: stride % dim4 == 0 guaranteed by host.
    int col4 = (int)(idx0 % (long long)dim4);
    int c = col4 * 4;

    float4 s;
    s.x = S[(long long)(c + 0) * dim + (c + 0)];
    s.y = S[(long long)(c + 1) * dim + (c + 1)];
    s.z = S[(long long)(c + 2) * dim + (c + 2)];
    s.w = S[(long long)(c + 3) * dim + (c + 3)];

    // Front-batch all loads: MLP = ITERS per thread.
    float4 v[ITERS];
    #pragma unroll
    for (int i = 0; i < ITERS; i++) {
        v[i] = __ldcg(&h[idx0 + (long long)i * stride]);
    }
    #pragma unroll
    for (int i = 0; i < ITERS; i++) {
        float4 r = v[i];
        r.x *= s.x; r.y *= s.y; r.z *= s.z; r.w *= s.w;
        out[idx0 + (long long)i * stride] = r;
    }
}

// ---------------- Generic fallback (R2 kernel) ------------------------------
__global__ void parity_scale_generic(const float4* __restrict__ h,
                                     const float* __restrict__ S,
                                     float4* __restrict__ out,
                                     long long n_vec4, int dim4, int dim) {
    long long idx0 = (long long)blockIdx.x * blockDim.x + threadIdx.x;
    long long stride = (long long)gridDim.x * blockDim.x;  // multiple of dim4

    int col4 = (int)(idx0 % (long long)dim4);
    int c = col4 * 4;

    float4 s;
    s.x = S[(long long)(c + 0) * dim + (c + 0)];
    s.y = S[(long long)(c + 1) * dim + (c + 1)];
    s.z = S[(long long)(c + 2) * dim + (c + 2)];
    s.w = S[(long long)(c + 3) * dim + (c + 3)];

    #pragma unroll 4
    for (long long idx = idx0; idx < n_vec4; idx += stride) {
        float4 v = __ldcg(&h[idx]);
        v.x *= s.x; v.y *= s.y; v.z *= s.z; v.w *= s.w;
        out[idx] = v;
    }
}

static long long gcd_ll(long long a, long long b) {
    while (b) { long long t = a % b; a = b; b = t; }
    return a;
}

extern "C" void kernel_launch(void* const* d_in, const int* in_sizes, int n_in,
                              void* d_out, int out_size) {
    const float* h = (const float*)d_in[0];
    const float* S = (const float*)d_in[1];
    float* out = (float*)d_out;

    // in_sizes[1] = DIM*DIM -> integer sqrt
    int dim = 1;
    {
        long long s = in_sizes[1];
        long long lo = 1, hi = 65536;
        while (lo < hi) {
            long long mid = (lo + hi + 1) / 2;
            if (mid * mid <= s) lo = mid; else hi = mid - 1;
        }
        dim = (int)lo;
    }

    long long total = in_sizes[0];        // N_ROWS * DIM
    long long n_vec4 = total / 4;
    int dim4 = dim / 4;

    const int threads = 256;

    // Try the specialized path: find blocks such that
    //   T = blocks*256 is a multiple of dim4, and n_vec4 == 8 * T.
    const int ITERS = 8;
    long long T = n_vec4 / ITERS;
    bool exact = (n_vec4 % ITERS == 0) &&
                 (T % threads == 0) &&
                 (T % dim4 == 0) &&
                 (T / threads <= 2147483647LL) &&
                 (dim % 4 == 0);

    if (exact) {
        int blocks = (int)(T / threads);
        parity_scale_exact<ITERS><<<blocks, threads>>>(
            (const float4*)h, S, (float4*)out, dim4, dim);
        return;
    }

    // Generic fallback: grid-stride multiple of dim4 (col invariance).
    long long m = (long long)dim4 / gcd_ll(threads, dim4);
    long long want = 148LL * 32;
    long long blocks = ((want + m - 1) / m) * m;
    long long cover = (n_vec4 + threads - 1) / threads;
    long long cover_r = ((cover + m - 1) / m) * m;
    if (blocks > cover_r) blocks = cover_r;
    if (blocks < m) blocks = m;

    parity_scale_generic<<<(int)blocks, threads>>>(
        (const float4*)h, S, (float4*)out, n_vec4, dim4, dim);
}